// round 16
// baseline (speedup 1.0000x reference)
#include <cuda_runtime.h>
#include <cuda_bf16.h>
#include <cstdint>
#include <math.h>

// ---------------- problem constants ----------------
#define BB   4
#define TT   4096
#define DD   1024
#define MM   64
#define NN   128
#define BT   (BB*TT)     // 16384
#define DT_C 0.01f
#define KX   1152        // concat K for out gemm: [xs(128) | u(1024)]

// ---------------- portable PTX helpers (sm_80+ ISA only) ----------------
__device__ __forceinline__ uint32_t smem_to_u32(const void* p) {
    uint32_t a;
    asm("{ .reg .u64 t; cvta.to.shared.u64 t, %1; cvt.u32.u64 %0, t; }" : "=r"(a) : "l"(p));
    return a;
}
#define CP_ASYNC16(SM, GM) \
    asm volatile("cp.async.cg.shared.global [%0], [%1], 16;" :: "r"(SM), "l"(GM) : "memory")
#define CP_COMMIT() asm volatile("cp.async.commit_group;" ::: "memory")
#define CP_WAIT0()  asm volatile("cp.async.wait_group 0;" ::: "memory")
#define LDSM_X4(R0,R1,R2,R3, ADDR) \
    asm volatile("ldmatrix.sync.aligned.m8n8.x4.shared.b16 {%0,%1,%2,%3}, [%4];" \
        : "=r"(R0),"=r"(R1),"=r"(R2),"=r"(R3) : "r"(ADDR))
#define MMA_BF16(D, A, B) \
    asm volatile("mma.sync.aligned.m16n8k16.row.col.f32.bf16.bf16.f32 " \
        "{%0,%1,%2,%3}, {%4,%5,%6,%7}, {%8,%9}, {%0,%1,%2,%3};" \
        : "+f"((D)[0]), "+f"((D)[1]), "+f"((D)[2]), "+f"((D)[3]) \
        : "r"((A)[0]), "r"((A)[1]), "r"((A)[2]), "r"((A)[3]), "r"((B)[0]), "r"((B)[1]))
#define MMA_TF32(D, A, B) \
    asm volatile("mma.sync.aligned.m16n8k8.row.col.f32.tf32.tf32.f32 " \
        "{%0,%1,%2,%3}, {%4,%5,%6,%7}, {%8,%9}, {%0,%1,%2,%3};" \
        : "+f"((D)[0]), "+f"((D)[1]), "+f"((D)[2]), "+f"((D)[3]) \
        : "r"((A)[0]), "r"((A)[1]), "r"((A)[2]), "r"((A)[3]), "r"((B)[0]), "r"((B)[1]))

// ---------------- scratch (static device, no allocation) ----------------
__device__ __align__(16) __nv_bfloat16 g_Wph[256*DD];         // proj W hi [256,1024]
__device__ __align__(16) __nv_bfloat16 g_Wpl[256*DD];
__device__ __align__(16) float g_G[(size_t)BT*256];           // proj result
__device__ __align__(16) float g_xs[(size_t)BT*NN];           // scan outputs fp32

__device__ __forceinline__ void split2(float x, __nv_bfloat16& h, __nv_bfloat16& l) {
    h = __float2bfloat16(x);
    l = __float2bfloat16(x - __bfloat162float(h));
}

// fast coefficients (clip makes underflow-safe)
__device__ __forceinline__ void coeffs(float go, float gz, float bom, float bzm,
                                       float& a, float& bb, float& cc)
{
    float vo = go + bom;
    float e = __expf(-fabsf(vo));
    float sp = fmaxf(vo, 0.f) + __logf(1.f + e);
    float omega = fminf(fmaxf(sp, 1e-4f), 100.0f);
    float vz = gz + bzm;
    float zeta = __fdividef(1.f, 1.f + __expf(-vz));
    float d = 1.f - zeta;
    float A = omega * omega;
    float S = __fdividef(1.f, 1.f + DT_C * DT_C * A);
    a  = d * S;
    bb = d * DT_C * A * S;
    cc = d * DT_C * S;
}

// ---------------- proj weight conversion (bf16 splits) ----------------
__global__ void conv_w(const float* __restrict__ Wo, const float* __restrict__ Wz,
                       const float* __restrict__ WB)
{
    int i = blockIdx.x * blockDim.x + threadIdx.x;   // over 256*256 float4s
    if (i >= 256 * 256) return;
    int row = i >> 8, c4 = i & 255;
    const float* src = (row < 64)  ? (Wo + (size_t)row * DD)
                     : (row < 128) ? (Wz + (size_t)(row - 64) * DD)
                                   : (WB + (size_t)(row - 128) * DD);
    float4 v = *reinterpret_cast<const float4*>(src + c4 * 4);
    union { __nv_bfloat16 b[4]; uint2 u2; } ph, pl;
    split2(v.x, ph.b[0], pl.b[0]); split2(v.y, ph.b[1], pl.b[1]);
    split2(v.z, ph.b[2], pl.b[2]); split2(v.w, ph.b[3], pl.b[3]);
    size_t o = (size_t)row * DD + c4 * 4;
    *reinterpret_cast<uint2*>(&g_Wph[o]) = ph.u2;
    *reinterpret_cast<uint2*>(&g_Wpl[o]) = pl.u2;
}

// ---------------- proj GEMM: split-bf16, on-the-fly A conversion -----------
#define TILEB   10240                 // 128 rows * 80B (32 bf16 + pad)
#define AF32B   16384                 // 128 rows * 32 fp32
#define S_BOFF   (2*AF32B)
#define S_AOFF   (S_BOFF + 4*TILEB)
#define GEMM_SMEM (S_AOFF + 2*TILEB)  // 94208

__global__ void __launch_bounds__(256, 2)
gemm_fused(const float* __restrict__ A1, int lda1,
           const float* __restrict__ A2, int lda2, int kSplit,
           const __nv_bfloat16* __restrict__ Bh, const __nv_bfloat16* __restrict__ Bl,
           float* __restrict__ Cout, int ldc, int K)
{
    extern __shared__ char smc[];
    const uint32_t sb = smem_to_u32(smc);
    const int tid = threadIdx.x;
    const int wid = tid >> 5, lane = tid & 31;
    const int warpM = wid & 3, warpN = wid >> 2;
    const int rowBase = blockIdx.y * 128;
    const int colBase = blockIdx.x * 128;

    auto load_A = [&](int stage, int k0) {
        const float* Ap; int ld, kc;
        if (k0 < kSplit) { Ap = A1; ld = lda1; kc = k0; }
        else             { Ap = A2; ld = lda2; kc = k0 - kSplit; }
#pragma unroll
        for (int i = 0; i < 4; i++) {
            int f = i * 256 + tid;
            int r = f >> 3, q = f & 7;
            uint32_t so = sb + stage * AF32B + f * 16;
            const float* g = Ap + (size_t)(rowBase + r) * ld + kc + q * 4;
            CP_ASYNC16(so, g);
        }
    };
    auto load_B = [&](int stage, int k0) {
#pragma unroll
        for (int i = 0; i < 4; i++) {
            int idx = i * 256 + tid;
            int tile = idx >> 9;               // 0=Bh, 1=Bl
            int e = idx & 511;
            int r = e >> 2, j = e & 3;
            uint32_t so = sb + S_BOFF + stage * 2 * TILEB + tile * TILEB + r * 80 + j * 16;
            const __nv_bfloat16* g = (tile ? Bl : Bh)
                + (size_t)(colBase + r) * K + k0 + j * 8;
            CP_ASYNC16(so, g);
        }
    };

    float acc[2][8][4];
#pragma unroll
    for (int a = 0; a < 2; a++)
#pragma unroll
        for (int b = 0; b < 8; b++)
#pragma unroll
            for (int c = 0; c < 4; c++) acc[a][b][c] = 0.f;

    const uint32_t aRowOff = (uint32_t)(lane & 15) * 80 + (uint32_t)(lane >> 4) * 16;
    const uint32_t bRowOff = (uint32_t)((lane & 7) + ((lane >> 4) & 1) * 8) * 80
                           + (uint32_t)((lane >> 3) & 1) * 16;

    const int nch = K / 32;
    load_A(0, 0); load_B(0, 0); CP_COMMIT();

    for (int c = 0; c < nch; c++) {
        CP_WAIT0();
        __syncthreads();
        if (c + 1 < nch) {
            load_A((c + 1) & 1, (c + 1) * 32);
            load_B((c + 1) & 1, (c + 1) * 32);
            CP_COMMIT();
        }
#pragma unroll
        for (int i = 0; i < 4; i++) {
            int f = i * 256 + tid;
            int r = f >> 3, q = f & 7;
            float4 v = *reinterpret_cast<const float4*>(smc + (c & 1) * AF32B + f * 16);
            union { __nv_bfloat16 b[4]; uint2 u2; } ph, pl;
            split2(v.x, ph.b[0], pl.b[0]); split2(v.y, ph.b[1], pl.b[1]);
            split2(v.z, ph.b[2], pl.b[2]); split2(v.w, ph.b[3], pl.b[3]);
            uint32_t dst = r * 80 + q * 8;
            *reinterpret_cast<uint2*>(smc + S_AOFF + dst)         = ph.u2;
            *reinterpret_cast<uint2*>(smc + S_AOFF + TILEB + dst) = pl.u2;
        }
        __syncthreads();
        const uint32_t stB = sb + S_BOFF + (c & 1) * 2 * TILEB;
        const uint32_t stA = sb + S_AOFF;
#pragma unroll
        for (int k16 = 0; k16 < 2; k16++) {
            const uint32_t kb = (uint32_t)k16 * 32;
            uint32_t ah[2][4], al[2][4];
#pragma unroll
            for (int mf = 0; mf < 2; mf++) {
                uint32_t base = stA + (uint32_t)(warpM * 32 + mf * 16) * 80 + kb + aRowOff;
                LDSM_X4(ah[mf][0], ah[mf][1], ah[mf][2], ah[mf][3], base);
                LDSM_X4(al[mf][0], al[mf][1], al[mf][2], al[mf][3], base + TILEB);
            }
#pragma unroll
            for (int p = 0; p < 4; p++) {
                uint32_t base = stB + (uint32_t)(warpN * 64 + p * 16) * 80 + kb + bRowOff;
                uint32_t bh[2][2], bl[2][2];
                uint32_t r0, r1, r2, r3;
                LDSM_X4(r0, r1, r2, r3, base);
                bh[0][0] = r0; bh[0][1] = r1; bh[1][0] = r2; bh[1][1] = r3;
                LDSM_X4(r0, r1, r2, r3, base + TILEB);
                bl[0][0] = r0; bl[0][1] = r1; bl[1][0] = r2; bl[1][1] = r3;
#pragma unroll
                for (int h = 0; h < 2; h++) {
                    int nf = 2 * p + h;
#pragma unroll
                    for (int mf = 0; mf < 2; mf++) {
                        MMA_BF16(acc[mf][nf], ah[mf], bh[h]);
                        MMA_BF16(acc[mf][nf], al[mf], bh[h]);
                        MMA_BF16(acc[mf][nf], ah[mf], bl[h]);
                    }
                }
            }
        }
    }

    const int row0 = rowBase + warpM * 32 + (lane >> 2);
    const int col0 = colBase + warpN * 64 + (lane & 3) * 2;
#pragma unroll
    for (int mf = 0; mf < 2; mf++)
#pragma unroll
        for (int nf = 0; nf < 8; nf++) {
            int r = row0 + mf * 16, cc = col0 + nf * 8;
            float2 v0 = make_float2(acc[mf][nf][0], acc[mf][nf][1]);
            float2 v1 = make_float2(acc[mf][nf][2], acc[mf][nf][3]);
            *reinterpret_cast<float2*>(&Cout[(size_t)r * ldc + cc]) = v0;
            *reinterpret_cast<float2*>(&Cout[(size_t)(r + 8) * ldc + cc]) = v1;
        }
}

// ---------------- out GEMM: plain tf32 (single product) --------------------
#define TFA     36
#define TFTILEB (128*TFA*4)            // 18432
#define TF_BOFF (2*TFTILEB)
#define TF_SMEM (4*TFTILEB)            // 73728

__device__ __forceinline__ uint32_t f2tf32(float x) {
    return __float_as_uint(x) + 0x1000u;
}

__global__ void __launch_bounds__(256, 2)
gemm_tf32(const float* __restrict__ A1, int lda1,
          const float* __restrict__ A2, int lda2, int kSplitA,
          const float* __restrict__ B1, int ldb1,
          const float* __restrict__ B2, int ldb2, int kSplitB,
          float* __restrict__ Cout, int ldc, int K)
{
    extern __shared__ char smc[];
    const uint32_t sb = smem_to_u32(smc);
    const int tid = threadIdx.x;
    const int wid = tid >> 5, lane = tid & 31;
    const int warpM = wid & 3, warpN = wid >> 2;
    const int rowBase = blockIdx.y * 128;
    const int colBase = blockIdx.x * 128;

    auto load_tile = [&](uint32_t soBase, const float* P1, int ld1,
                         const float* P2, int ld2, int kSplit,
                         int rbase, int k0) {
        const float* Ap; int ld, kc;
        if (k0 < kSplit) { Ap = P1; ld = ld1; kc = k0; }
        else             { Ap = P2; ld = ld2; kc = k0 - kSplit; }
#pragma unroll
        for (int i = 0; i < 4; i++) {
            int f = i * 256 + tid;
            int r = f >> 3, q = f & 7;
            uint32_t so = soBase + r * (TFA * 4) + q * 16;
            CP_ASYNC16(so, Ap + (size_t)(rbase + r) * ld + kc + q * 4);
        }
    };

    float acc[2][8][4];
#pragma unroll
    for (int a = 0; a < 2; a++)
#pragma unroll
        for (int b = 0; b < 8; b++)
#pragma unroll
            for (int c = 0; c < 4; c++) acc[a][b][c] = 0.f;

    const int nch = K / 32;
    load_tile(sb, A1, lda1, A2, lda2, kSplitA, rowBase, 0);
    load_tile(sb + TF_BOFF, B1, ldb1, B2, ldb2, kSplitB, colBase, 0);
    CP_COMMIT();

    const int lr = lane >> 2;
    const int lc = lane & 3;

    for (int c = 0; c < nch; c++) {
        CP_WAIT0();
        __syncthreads();
        if (c + 1 < nch) {
            load_tile(sb + ((c + 1) & 1) * TFTILEB, A1, lda1, A2, lda2, kSplitA,
                      rowBase, (c + 1) * 32);
            load_tile(sb + TF_BOFF + ((c + 1) & 1) * TFTILEB, B1, ldb1, B2, ldb2, kSplitB,
                      colBase, (c + 1) * 32);
            CP_COMMIT();
        }
        const float* As = reinterpret_cast<const float*>(smc + (c & 1) * TFTILEB);
        const float* Bs = reinterpret_cast<const float*>(smc + TF_BOFF + (c & 1) * TFTILEB);
#pragma unroll
        for (int j = 0; j < 4; j++) {
            const int kb = j * 8;
            uint32_t a[2][4];
#pragma unroll
            for (int mf = 0; mf < 2; mf++) {
                int r1 = warpM * 32 + mf * 16 + lr;
                a[mf][0] = f2tf32(As[r1 * TFA + kb + lc]);
                a[mf][1] = f2tf32(As[(r1 + 8) * TFA + kb + lc]);
                a[mf][2] = f2tf32(As[r1 * TFA + kb + lc + 4]);
                a[mf][3] = f2tf32(As[(r1 + 8) * TFA + kb + lc + 4]);
            }
#pragma unroll
            for (int nf = 0; nf < 8; nf++) {
                int n = warpN * 64 + nf * 8 + lr;
                uint32_t b[2];
                b[0] = f2tf32(Bs[n * TFA + kb + lc]);
                b[1] = f2tf32(Bs[n * TFA + kb + lc + 4]);
#pragma unroll
                for (int mf = 0; mf < 2; mf++)
                    MMA_TF32(acc[mf][nf], a[mf], b);
            }
        }
    }

    const int row0 = rowBase + warpM * 32 + lr;
    const int col0 = colBase + warpN * 64 + lc * 2;
#pragma unroll
    for (int mf = 0; mf < 2; mf++)
#pragma unroll
        for (int nf = 0; nf < 8; nf++) {
            int r = row0 + mf * 16, cc = col0 + nf * 8;
            float2 v0 = make_float2(acc[mf][nf][0], acc[mf][nf][1]);
            float2 v1 = make_float2(acc[mf][nf][2], acc[mf][nf][3]);
            *reinterpret_cast<float2*>(&Cout[(size_t)r * ldc + cc]) = v0;
            *reinterpret_cast<float2*>(&Cout[(size_t)(r + 8) * ldc + cc]) = v1;
        }
}

// ---------------- fused scan: one warp owns one (b,m), full T --------------
// grid (64, 4), 32 threads. Per 128-t segment: lane composes 4 consecutive
// per-t affine transforms locally, Kogge-Stone over lanes, carry in regs.
__global__ void __launch_bounds__(32)
scan_fused(const float* __restrict__ bo, const float* __restrict__ bz,
           const float* __restrict__ bB)
{
    const int m = blockIdx.x;          // 0..63
    const int b = blockIdx.y;          // 0..3
    const int lane = threadIdx.x;
    const float bom = bo[m], bzm = bz[m], bBz = bB[m], bBy = bB[64 + m];
    const float* Gb = g_G + (size_t)b * TT * 256;
    float* xsb = g_xs + (size_t)b * TT * NN;

    float cz = 0.f, cy = 0.f;          // carry state x_{t0-1}

    // prefetch buffers (segment data: 4 t per lane x 4 values)
    float pgo[4], pgz[4], pFz[4], pFy[4];
#pragma unroll
    for (int j = 0; j < 4; j++) {
        const float* Gr = Gb + (size_t)(lane * 4 + j) * 256;
        pgo[j] = Gr[m]; pgz[j] = Gr[64 + m]; pFz[j] = Gr[128 + m]; pFy[j] = Gr[192 + m];
    }

    for (int seg = 0; seg < TT / 128; seg++) {
        float a[4], bb[4], cc[4], Fz[4], Fy[4];
#pragma unroll
        for (int j = 0; j < 4; j++) {
            coeffs(pgo[j], pgz[j], bom, bzm, a[j], bb[j], cc[j]);
            Fz[j] = pFz[j] + bBz;
            Fy[j] = pFy[j] + bBy;
        }
        // prefetch next segment
        if (seg + 1 < TT / 128) {
            const float* Gn = Gb + (size_t)((seg + 1) * 128 + lane * 4) * 256;
#pragma unroll
            for (int j = 0; j < 4; j++) {
                const float* Gr = Gn + (size_t)j * 256;
                pgo[j] = Gr[m]; pgz[j] = Gr[64 + m];
                pFz[j] = Gr[128 + m]; pFy[j] = Gr[192 + m];
            }
        }
        // local inclusive compose over the lane's 4 transforms
        float P00 = a[0], P01 = -bb[0], P10 = cc[0], P11 = a[0];
        float qz = Fz[0], qy = Fy[0];
#pragma unroll
        for (int j = 1; j < 4; j++) {
            float n00 = a[j]*P00 - bb[j]*P10, n01 = a[j]*P01 - bb[j]*P11;
            float n10 = cc[j]*P00 + a[j]*P10, n11 = cc[j]*P01 + a[j]*P11;
            float nz  = a[j]*qz - bb[j]*qy + Fz[j];
            float ny  = cc[j]*qz + a[j]*qy + Fy[j];
            P00=n00; P01=n01; P10=n10; P11=n11; qz=nz; qy=ny;
        }
        // Kogge-Stone inclusive over lanes (t order = lane order)
#pragma unroll
        for (int d = 1; d < 32; d <<= 1) {
            float s00 = __shfl_up_sync(0xffffffffu, P00, d);
            float s01 = __shfl_up_sync(0xffffffffu, P01, d);
            float s10 = __shfl_up_sync(0xffffffffu, P10, d);
            float s11 = __shfl_up_sync(0xffffffffu, P11, d);
            float sqz = __shfl_up_sync(0xffffffffu, qz, d);
            float sqy = __shfl_up_sync(0xffffffffu, qy, d);
            if (lane >= d) {
                float n00 = P00*s00 + P01*s10, n01 = P00*s01 + P01*s11;
                float n10 = P10*s00 + P11*s10, n11 = P10*s01 + P11*s11;
                float nz  = P00*sqz + P01*sqy + qz;
                float ny  = P10*sqz + P11*sqy + qy;
                P00=n00; P01=n01; P10=n10; P11=n11; qz=nz; qy=ny;
            }
        }
        // exclusive transform for this lane (identity at lane 0)
        float e00 = __shfl_up_sync(0xffffffffu, P00, 1);
        float e01 = __shfl_up_sync(0xffffffffu, P01, 1);
        float e10 = __shfl_up_sync(0xffffffffu, P10, 1);
        float e11 = __shfl_up_sync(0xffffffffu, P11, 1);
        float eqz = __shfl_up_sync(0xffffffffu, qz, 1);
        float eqy = __shfl_up_sync(0xffffffffu, qy, 1);
        if (lane == 0) { e00 = 1.f; e01 = 0.f; e10 = 0.f; e11 = 1.f; eqz = 0.f; eqy = 0.f; }
        // state entering this lane's 4 t's
        float sz = e00*cz + e01*cy + eqz;
        float sy = e10*cz + e11*cy + eqy;
        // serial apply + store
        size_t t0 = (size_t)(seg * 128 + lane * 4);
#pragma unroll
        for (int j = 0; j < 4; j++) {
            float nz = a[j]*sz - bb[j]*sy + Fz[j];
            float ny = cc[j]*sz + a[j]*sy + Fy[j];
            sz = nz; sy = ny;
            size_t xo = (t0 + j) * NN;
            xsb[xo + m]      = sz;
            xsb[xo + 64 + m] = sy;
        }
        // carry update from lane 31's inclusive transform
        float t00 = __shfl_sync(0xffffffffu, P00, 31);
        float t01 = __shfl_sync(0xffffffffu, P01, 31);
        float t10 = __shfl_sync(0xffffffffu, P10, 31);
        float t11 = __shfl_sync(0xffffffffu, P11, 31);
        float tqz = __shfl_sync(0xffffffffu, qz, 31);
        float tqy = __shfl_sync(0xffffffffu, qy, 31);
        float ncz = t00*cz + t01*cy + tqz;
        float ncy = t10*cz + t11*cy + tqy;
        cz = ncz; cy = ncy;
    }
}

// ---------------- launch ----------------
extern "C" void kernel_launch(void* const* d_in, const int* in_sizes, int n_in,
                              void* d_out, int out_size)
{
    const float* u   = (const float*)d_in[0];
    const float* Wo  = (const float*)d_in[1];
    const float* bo  = (const float*)d_in[2];
    const float* Wz  = (const float*)d_in[3];
    const float* bz  = (const float*)d_in[4];
    const float* WB  = (const float*)d_in[5];
    const float* bBv = (const float*)d_in[6];
    const float* Cm  = (const float*)d_in[7];
    const float* Dm  = (const float*)d_in[8];
    float* out = (float*)d_out;

    static int configured = 0;
    if (!configured) {
        cudaFuncSetAttribute(gemm_fused, cudaFuncAttributeMaxDynamicSharedMemorySize, GEMM_SMEM);
        cudaFuncSetAttribute(gemm_tf32, cudaFuncAttributeMaxDynamicSharedMemorySize, TF_SMEM);
        configured = 1;
    }

    __nv_bfloat16 *Wph, *Wpl; float *G, *Xs;
    cudaGetSymbolAddress((void**)&Wph, g_Wph);
    cudaGetSymbolAddress((void**)&Wpl, g_Wpl);
    cudaGetSymbolAddress((void**)&G,   g_G);
    cudaGetSymbolAddress((void**)&Xs,  g_xs);

    // 1. proj weight split conversion
    conv_w<<<(256 * 256 + 255) / 256, 256>>>(Wo, Wz, WB);

    // 2. projection GEMM (split-bf16, precision preserved for scan path)
    gemm_fused<<<dim3(256 / 128, BT / 128), 256, GEMM_SMEM>>>(
        u, DD, u, DD, /*kSplit=*/2048, Wph, Wpl, G, 256, DD);

    // 3. single-kernel fused activation + scan (warp per (b,m))
    scan_fused<<<dim3(MM, BB), 32>>>(bo, bz, bBv);

    // 4. output GEMM: plain tf32, A=[xs|u], B=[C|D] read directly as fp32
    gemm_tf32<<<dim3(DD / 128, BT / 128), 256, TF_SMEM>>>(
        Xs, NN, u, DD, /*kSplitA=*/128,
        Cm, NN, Dm, DD, /*kSplitB=*/128,
        out, DD, KX);
}

// round 17
// speedup vs baseline: 1.1376x; 1.1376x over previous
#include <cuda_runtime.h>
#include <cuda_bf16.h>
#include <cstdint>
#include <math.h>

// ---------------- problem constants ----------------
#define BB   4
#define TT   4096
#define DD   1024
#define MM   64
#define NN   128
#define BT   (BB*TT)     // 16384
#define DT_C 0.01f
#define CHUNK 16
#define NCH  (TT/CHUNK)  // 256
#define KX   1152        // concat K for out gemm: [xs(128) | u(1024)]

// ---------------- portable PTX helpers (sm_80+ ISA only) ----------------
__device__ __forceinline__ uint32_t smem_to_u32(const void* p) {
    uint32_t a;
    asm("{ .reg .u64 t; cvta.to.shared.u64 t, %1; cvt.u32.u64 %0, t; }" : "=r"(a) : "l"(p));
    return a;
}
#define CP_ASYNC16(SM, GM) \
    asm volatile("cp.async.cg.shared.global [%0], [%1], 16;" :: "r"(SM), "l"(GM) : "memory")
#define CP_COMMIT() asm volatile("cp.async.commit_group;" ::: "memory")
#define CP_WAIT0()  asm volatile("cp.async.wait_group 0;" ::: "memory")
#define MMA_TF32(D, A, B) \
    asm volatile("mma.sync.aligned.m16n8k8.row.col.f32.tf32.tf32.f32 " \
        "{%0,%1,%2,%3}, {%4,%5,%6,%7}, {%8,%9}, {%0,%1,%2,%3};" \
        : "+f"((D)[0]), "+f"((D)[1]), "+f"((D)[2]), "+f"((D)[3]) \
        : "r"((A)[0]), "r"((A)[1]), "r"((A)[2]), "r"((A)[3]), "r"((B)[0]), "r"((B)[1]))

// ---------------- scratch (static device, no allocation) ----------------
__device__ __align__(16) float g_Wp[256*DD];                  // proj W concat fp32
__device__ __align__(16) float g_G[(size_t)BT*256];           // proj result
__device__ __align__(16) float g_xs[(size_t)BT*NN];           // scan outputs fp32
__device__ __align__(16) float g_ca[(size_t)BT*MM];           // coeff cache
__device__ __align__(16) float g_cb[(size_t)BT*MM];
__device__ __align__(16) float g_cc[(size_t)BT*MM];
// chunk summaries, layout [b][m][ch] (ch fastest -> coalesced warp scan)
__device__ __align__(16) float g_P00[BB*MM*NCH], g_P01[BB*MM*NCH];
__device__ __align__(16) float g_P10[BB*MM*NCH], g_P11[BB*MM*NCH];
__device__ __align__(16) float g_qz[BB*MM*NCH],  g_qy[BB*MM*NCH];
__device__ __align__(16) float g_iz[BB*MM*NCH],  g_iy[BB*MM*NCH];

// fast coefficients (clip makes underflow-safe)
__device__ __forceinline__ void coeffs(float go, float gz, float bom, float bzm,
                                       float& a, float& bb, float& cc)
{
    float vo = go + bom;
    float e = __expf(-fabsf(vo));
    float sp = fmaxf(vo, 0.f) + __logf(1.f + e);
    float omega = fminf(fmaxf(sp, 1e-4f), 100.0f);
    float vz = gz + bzm;
    float zeta = __fdividef(1.f, 1.f + __expf(-vz));
    float d = 1.f - zeta;
    float A = omega * omega;
    float S = __fdividef(1.f, 1.f + DT_C * DT_C * A);
    a  = d * S;
    bb = d * DT_C * A * S;
    cc = d * DT_C * S;
}

// ---------------- proj weight concat (fp32 copy, rows [Wo;Wz;WB]) ----------
__global__ void conv_wp(const float* __restrict__ Wo, const float* __restrict__ Wz,
                        const float* __restrict__ WB)
{
    int i = blockIdx.x * blockDim.x + threadIdx.x;   // over 256*256 float4s
    if (i >= 256 * 256) return;
    int row = i >> 8, c4 = i & 255;
    const float* src = (row < 64)  ? (Wo + (size_t)row * DD)
                     : (row < 128) ? (Wz + (size_t)(row - 64) * DD)
                                   : (WB + (size_t)(row - 128) * DD);
    float4 v = *reinterpret_cast<const float4*>(src + c4 * 4);
    *reinterpret_cast<float4*>(&g_Wp[(size_t)row * DD + c4 * 4]) = v;
}

// ---------------- GEMM: plain tf32 (single product) ------------------------
// C[M,N] = A * B^T in tf32, fp32 accum. A,B fp32, each split over two row-major
// sources at chunk-aligned kSplit. smem rows of 36 fp32 (144B, conflict-free).
#define TFA     36
#define TFTILEB (128*TFA*4)            // 18432
#define TF_BOFF (2*TFTILEB)
#define TF_SMEM (4*TFTILEB)            // 73728

__device__ __forceinline__ uint32_t f2tf32(float x) {
    return __float_as_uint(x) + 0x1000u;
}

__global__ void __launch_bounds__(256, 2)
gemm_tf32(const float* __restrict__ A1, int lda1,
          const float* __restrict__ A2, int lda2, int kSplitA,
          const float* __restrict__ B1, int ldb1,
          const float* __restrict__ B2, int ldb2, int kSplitB,
          float* __restrict__ Cout, int ldc, int K)
{
    extern __shared__ char smc[];
    const uint32_t sb = smem_to_u32(smc);
    const int tid = threadIdx.x;
    const int wid = tid >> 5, lane = tid & 31;
    const int warpM = wid & 3, warpN = wid >> 2;
    const int rowBase = blockIdx.y * 128;
    const int colBase = blockIdx.x * 128;

    auto load_tile = [&](uint32_t soBase, const float* P1, int ld1,
                         const float* P2, int ld2, int kSplit,
                         int rbase, int k0) {
        const float* Ap; int ld, kc;
        if (k0 < kSplit) { Ap = P1; ld = ld1; kc = k0; }
        else             { Ap = P2; ld = ld2; kc = k0 - kSplit; }
#pragma unroll
        for (int i = 0; i < 4; i++) {
            int f = i * 256 + tid;
            int r = f >> 3, q = f & 7;
            uint32_t so = soBase + r * (TFA * 4) + q * 16;
            CP_ASYNC16(so, Ap + (size_t)(rbase + r) * ld + kc + q * 4);
        }
    };

    float acc[2][8][4];
#pragma unroll
    for (int a = 0; a < 2; a++)
#pragma unroll
        for (int b = 0; b < 8; b++)
#pragma unroll
            for (int c = 0; c < 4; c++) acc[a][b][c] = 0.f;

    const int nch = K / 32;
    load_tile(sb, A1, lda1, A2, lda2, kSplitA, rowBase, 0);
    load_tile(sb + TF_BOFF, B1, ldb1, B2, ldb2, kSplitB, colBase, 0);
    CP_COMMIT();

    const int lr = lane >> 2;
    const int lc = lane & 3;

    for (int c = 0; c < nch; c++) {
        CP_WAIT0();
        __syncthreads();
        if (c + 1 < nch) {
            load_tile(sb + ((c + 1) & 1) * TFTILEB, A1, lda1, A2, lda2, kSplitA,
                      rowBase, (c + 1) * 32);
            load_tile(sb + TF_BOFF + ((c + 1) & 1) * TFTILEB, B1, ldb1, B2, ldb2, kSplitB,
                      colBase, (c + 1) * 32);
            CP_COMMIT();
        }
        const float* As = reinterpret_cast<const float*>(smc + (c & 1) * TFTILEB);
        const float* Bs = reinterpret_cast<const float*>(smc + TF_BOFF + (c & 1) * TFTILEB);
#pragma unroll
        for (int j = 0; j < 4; j++) {
            const int kb = j * 8;
            uint32_t a[2][4];
#pragma unroll
            for (int mf = 0; mf < 2; mf++) {
                int r1 = warpM * 32 + mf * 16 + lr;
                a[mf][0] = f2tf32(As[r1 * TFA + kb + lc]);
                a[mf][1] = f2tf32(As[(r1 + 8) * TFA + kb + lc]);
                a[mf][2] = f2tf32(As[r1 * TFA + kb + lc + 4]);
                a[mf][3] = f2tf32(As[(r1 + 8) * TFA + kb + lc + 4]);
            }
#pragma unroll
            for (int nf = 0; nf < 8; nf++) {
                int n = warpN * 64 + nf * 8 + lr;
                uint32_t b[2];
                b[0] = f2tf32(Bs[n * TFA + kb + lc]);
                b[1] = f2tf32(Bs[n * TFA + kb + lc + 4]);
#pragma unroll
                for (int mf = 0; mf < 2; mf++)
                    MMA_TF32(acc[mf][nf], a[mf], b);
            }
        }
    }

    const int row0 = rowBase + warpM * 32 + lr;
    const int col0 = colBase + warpN * 64 + lc * 2;
#pragma unroll
    for (int mf = 0; mf < 2; mf++)
#pragma unroll
        for (int nf = 0; nf < 8; nf++) {
            int r = row0 + mf * 16, cc = col0 + nf * 8;
            float2 v0 = make_float2(acc[mf][nf][0], acc[mf][nf][1]);
            float2 v1 = make_float2(acc[mf][nf][2], acc[mf][nf][3]);
            *reinterpret_cast<float2*>(&Cout[(size_t)r * ldc + cc]) = v0;
            *reinterpret_cast<float2*>(&Cout[(size_t)(r + 8) * ldc + cc]) = v1;
        }
}

// summary index: [b][m][ch], ch fastest
#define CIDX(b, m, ch) (((b) * MM + (m)) * NCH + (ch))

// ---------------- scan phase 1: act (once) + coeff cache + summaries -------
__global__ void scan_phase1(const float* __restrict__ bo, const float* __restrict__ bz,
                            const float* __restrict__ bB)
{
    int b = blockIdx.y, ch = blockIdx.x, m = threadIdx.x;
    const float bom = bo[m], bzm = bz[m], bBz = bB[m], bBy = bB[64 + m];
    const size_t rt0 = (size_t)b * TT + ch * CHUNK;
    const float* Gp = g_G + rt0 * 256;
    float P00 = 1.f, P01 = 0.f, P10 = 0.f, P11 = 1.f, qz = 0.f, qy = 0.f;
#pragma unroll 4
    for (int s = 0; s < CHUNK; s++) {
        const float* Gr = Gp + (size_t)s * 256;
        float go = Gr[m], gz = Gr[64 + m];
        float Fz = Gr[128 + m] + bBz;
        float Fy = Gr[192 + m] + bBy;
        float a, bb, cc;
        coeffs(go, gz, bom, bzm, a, bb, cc);
        size_t co = (rt0 + s) * MM + m;
        g_ca[co] = a; g_cb[co] = bb; g_cc[co] = cc;
        float n00 = a*P00 - bb*P10, n01 = a*P01 - bb*P11;
        float n10 = cc*P00 + a*P10, n11 = cc*P01 + a*P11;
        float nqz = a*qz - bb*qy + Fz;
        float nqy = cc*qz + a*qy + Fy;
        P00=n00; P01=n01; P10=n10; P11=n11; qz=nqz; qy=nqy;
    }
    int ci = CIDX(b, m, ch);
    g_P00[ci]=P00; g_P01[ci]=P01; g_P10[ci]=P10; g_P11[ci]=P11;
    g_qz[ci]=qz;   g_qy[ci]=qy;
}

// ---------------- scan phase 2: warp scan over chunks, coalesced -----------
__global__ void scan_phase2()
{
    int gw = (blockIdx.x * blockDim.x + threadIdx.x) >> 5;   // 0..255
    int lane = threadIdx.x & 31;
    int base = gw * NCH + lane * 8;

    float lp00[8], lp01[8], lp10[8], lp11[8], lqz[8], lqy[8];
#pragma unroll
    for (int h = 0; h < 2; h++) {
        float4 f00 = *reinterpret_cast<const float4*>(&g_P00[base + h * 4]);
        float4 f01 = *reinterpret_cast<const float4*>(&g_P01[base + h * 4]);
        float4 f10 = *reinterpret_cast<const float4*>(&g_P10[base + h * 4]);
        float4 f11 = *reinterpret_cast<const float4*>(&g_P11[base + h * 4]);
        float4 fqz = *reinterpret_cast<const float4*>(&g_qz[base + h * 4]);
        float4 fqy = *reinterpret_cast<const float4*>(&g_qy[base + h * 4]);
        lp00[h*4+0]=f00.x; lp00[h*4+1]=f00.y; lp00[h*4+2]=f00.z; lp00[h*4+3]=f00.w;
        lp01[h*4+0]=f01.x; lp01[h*4+1]=f01.y; lp01[h*4+2]=f01.z; lp01[h*4+3]=f01.w;
        lp10[h*4+0]=f10.x; lp10[h*4+1]=f10.y; lp10[h*4+2]=f10.z; lp10[h*4+3]=f10.w;
        lp11[h*4+0]=f11.x; lp11[h*4+1]=f11.y; lp11[h*4+2]=f11.z; lp11[h*4+3]=f11.w;
        lqz[h*4+0]=fqz.x;  lqz[h*4+1]=fqz.y;  lqz[h*4+2]=fqz.z;  lqz[h*4+3]=fqz.w;
        lqy[h*4+0]=fqy.x;  lqy[h*4+1]=fqy.y;  lqy[h*4+2]=fqy.z;  lqy[h*4+3]=fqy.w;
    }

    float P00 = 1.f, P01 = 0.f, P10 = 0.f, P11 = 1.f, qz = 0.f, qy = 0.f;
#pragma unroll
    for (int j = 0; j < 8; j++) {
        float p00 = lp00[j], p01 = lp01[j], p10 = lp10[j], p11 = lp11[j];
        float vz = lqz[j], vy = lqy[j];
        float n00 = p00*P00 + p01*P10, n01 = p00*P01 + p01*P11;
        float n10 = p10*P00 + p11*P10, n11 = p10*P01 + p11*P11;
        float nz  = p00*qz + p01*qy + vz;
        float ny  = p10*qz + p11*qy + vy;
        P00=n00; P01=n01; P10=n10; P11=n11; qz=nz; qy=ny;
    }
#pragma unroll
    for (int d = 1; d < 32; d <<= 1) {
        float s00 = __shfl_up_sync(0xffffffffu, P00, d);
        float s01 = __shfl_up_sync(0xffffffffu, P01, d);
        float s10 = __shfl_up_sync(0xffffffffu, P10, d);
        float s11 = __shfl_up_sync(0xffffffffu, P11, d);
        float sqz = __shfl_up_sync(0xffffffffu, qz, d);
        float sqy = __shfl_up_sync(0xffffffffu, qy, d);
        if (lane >= d) {
            float n00 = P00*s00 + P01*s10, n01 = P00*s01 + P01*s11;
            float n10 = P10*s00 + P11*s10, n11 = P10*s01 + P11*s11;
            float nz  = P00*sqz + P01*sqy + qz;
            float ny  = P10*sqz + P11*sqy + qy;
            P00=n00; P01=n01; P10=n10; P11=n11; qz=nz; qy=ny;
        }
    }
    float z = __shfl_up_sync(0xffffffffu, qz, 1);
    float y = __shfl_up_sync(0xffffffffu, qy, 1);
    if (lane == 0) { z = 0.f; y = 0.f; }
    float oz[8], oy[8];
#pragma unroll
    for (int j = 0; j < 8; j++) {
        oz[j] = z; oy[j] = y;
        float nz = lp00[j]*z + lp01[j]*y + lqz[j];
        float ny = lp10[j]*z + lp11[j]*y + lqy[j];
        z = nz; y = ny;
    }
#pragma unroll
    for (int h = 0; h < 2; h++) {
        *reinterpret_cast<float4*>(&g_iz[base + h * 4]) =
            make_float4(oz[h*4+0], oz[h*4+1], oz[h*4+2], oz[h*4+3]);
        *reinterpret_cast<float4*>(&g_iy[base + h * 4]) =
            make_float4(oy[h*4+0], oy[h*4+1], oy[h*4+2], oy[h*4+3]);
    }
}

// ---------------- scan phase 3: replay from cached coeffs ------------------
__global__ void scan_phase3(const float* __restrict__ bB)
{
    int b = blockIdx.y, ch = blockIdx.x, m = threadIdx.x;
    const float bBz = bB[m], bBy = bB[64 + m];
    const size_t rt0 = (size_t)b * TT + ch * CHUNK;
    const float* Gp = g_G + rt0 * 256;
    int ci = CIDX(b, m, ch);
    float z = g_iz[ci], y = g_iy[ci];
#pragma unroll 4
    for (int s = 0; s < CHUNK; s++) {
        const float* Gr = Gp + (size_t)s * 256;
        size_t co = (rt0 + s) * MM + m;
        float a  = g_ca[co];
        float bb = g_cb[co];
        float cc = g_cc[co];
        float Fz = Gr[128 + m] + bBz;
        float Fy = Gr[192 + m] + bBy;
        float nz = a*z - bb*y + Fz;
        float ny = cc*z + a*y + Fy;
        z = nz; y = ny;
        size_t xo = (rt0 + s) * NN;
        g_xs[xo + m]      = z;
        g_xs[xo + 64 + m] = y;
    }
}

// ---------------- launch ----------------
extern "C" void kernel_launch(void* const* d_in, const int* in_sizes, int n_in,
                              void* d_out, int out_size)
{
    const float* u   = (const float*)d_in[0];
    const float* Wo  = (const float*)d_in[1];
    const float* bo  = (const float*)d_in[2];
    const float* Wz  = (const float*)d_in[3];
    const float* bz  = (const float*)d_in[4];
    const float* WB  = (const float*)d_in[5];
    const float* bBv = (const float*)d_in[6];
    const float* Cm  = (const float*)d_in[7];
    const float* Dm  = (const float*)d_in[8];
    float* out = (float*)d_out;

    static int configured = 0;
    if (!configured) {
        cudaFuncSetAttribute(gemm_tf32, cudaFuncAttributeMaxDynamicSharedMemorySize, TF_SMEM);
        configured = 1;
    }

    float *Wp, *G, *Xs;
    cudaGetSymbolAddress((void**)&Wp, g_Wp);
    cudaGetSymbolAddress((void**)&G,  g_G);
    cudaGetSymbolAddress((void**)&Xs, g_xs);

    // 1. proj weight concat (fp32 copy, tiny)
    conv_wp<<<(256 * 256 + 255) / 256, 256>>>(Wo, Wz, WB);

    // 2. projection GEMM: tf32, G[BT,256] = u @ Wp^T
    gemm_tf32<<<dim3(256 / 128, BT / 128), 256, TF_SMEM>>>(
        u, DD, u, DD, /*kSplitA=*/2048,
        Wp, DD, Wp, DD, /*kSplitB=*/2048,
        G, 256, DD);

    // 3. fused activation + chunked parallel scan (3-phase, R10 config)
    scan_phase1<<<dim3(NCH, BB), MM>>>(bo, bz, bBv);
    scan_phase2<<<8, 1024>>>();
    scan_phase3<<<dim3(NCH, BB), MM>>>(bBv);

    // 4. output GEMM: tf32, A=[xs|u], B=[C|D] read directly as fp32
    gemm_tf32<<<dim3(DD / 128, BT / 128), 256, TF_SMEM>>>(
        Xs, NN, u, DD, /*kSplitA=*/128,
        Cm, NN, Dm, DD, /*kSplitB=*/128,
        out, DD, KX);
}